// round 4
// baseline (speedup 1.0000x reference)
#include <cuda_runtime.h>
#include <math.h>

#define NN   1024
#define F    32
#define HID  64
#define OUTD 32

#define ITILE 4
#define JTILE 128
#define THREADS 128
#define PPT 4              // pairs (j's) per thread

// Scratch for the precomputed half-GEMMs (device globals: allowed, no allocs)
__device__ float g_A[NN * HID];   // A[i][h] = Emb[i,:] . W1[h, 0:F]
__device__ float g_B[NN * HID];   // B[j][h] = Emb[j,:] . W1[h, F:2F]

__global__ void precompute_AB(const float* __restrict__ Emb,
                              const float* __restrict__ W1) {
    int gid = blockIdx.x * blockDim.x + threadIdx.x;   // 0 .. NN*HID-1
    if (gid >= NN * HID) return;
    int i = gid >> 6;          // /HID
    int h = gid & (HID - 1);
    const float* e  = Emb + i * F;
    const float* w1 = W1 + h * (2 * F);
    float a = 0.f, b = 0.f;
#pragma unroll
    for (int f = 0; f < F; ++f) {
        float ev = e[f];
        a = fmaf(ev, w1[f],     a);
        b = fmaf(ev, w1[F + f], b);
    }
    g_A[gid] = a;
    g_B[gid] = b;
}

__device__ __forceinline__ float swish_f(float x) {
    float e   = __expf(-x);
    float sig = __fdividef(1.0f, 1.0f + e);
    return x * sig;
}

__global__ void __launch_bounds__(THREADS, 3)
fused_phi_kernel(const float* __restrict__ Edges,
                 const float* __restrict__ Coords,
                 const float* __restrict__ b1,
                 const float* __restrict__ W2,     // (OUTD, HID) row-major
                 const float* __restrict__ b2,
                 float* __restrict__ out)          // (NN, NN, OUTD)
{
    __shared__ __align__(16) float Bs[HID][JTILE + 1];   // [h][j], pad -> conflict-free
    __shared__ __align__(16) float W2Ts[HID][36];        // [h][o], row = 144B (16B-aligned)
    __shared__ float As[ITILE][HID];
    __shared__ float b1s[HID];
    __shared__ float b2s[OUTD];
    __shared__ float cjs[JTILE][3];
    __shared__ float cis[ITILE][3];

    const int tid = threadIdx.x;
    const int tj  = tid & 31;
    const int ti  = tid >> 5;
    const int j0  = blockIdx.x * JTILE;
    const int i0  = blockIdx.y * ITILE;
    const int i   = i0 + ti;

    // ---- stage tiles ----
    for (int idx = tid; idx < JTILE * HID; idx += THREADS) {
        int j = idx >> 6, h = idx & (HID - 1);
        Bs[h][j] = g_B[(j0 + j) * HID + h];
    }
    for (int idx = tid; idx < ITILE * HID; idx += THREADS) {
        As[idx >> 6][idx & (HID - 1)] = g_A[(i0 + (idx >> 6)) * HID + (idx & (HID - 1))];
    }
    for (int idx = tid; idx < OUTD * HID; idx += THREADS) {
        int o = idx >> 6, h = idx & (HID - 1);
        W2Ts[h][o] = W2[idx];                 // W2[o][h], idx = o*HID + h
    }
    if (tid < HID)  b1s[tid] = b1[tid];
    if (tid < OUTD) b2s[tid] = b2[tid];
    for (int idx = tid; idx < JTILE * 3; idx += THREADS)
        cjs[idx / 3][idx % 3] = Coords[(j0 + idx / 3) * 3 + idx % 3];
    if (tid < ITILE * 3)
        cis[tid / 3][tid % 3] = Coords[(i0 + tid / 3) * 3 + tid % 3];
    __syncthreads();

    // ---- per-pair weight w = Edges * dist ----
    float wv[PPT];
    const float cx = cis[ti][0], cy = cis[ti][1], cz = cis[ti][2];
#pragma unroll
    for (int p = 0; p < PPT; ++p) {
        int jl = tj + 32 * p;
        float dx = cx - cjs[jl][0];
        float dy = cy - cjs[jl][1];
        float dz = cz - cjs[jl][2];
        float sq = fmaf(dx, dx, fmaf(dy, dy, dz * dz));
        float dist = sqrtf(sq);               // sqrtf(0)=0 matches the guarded ref
        wv[p] = Edges[(size_t)i * NN + (j0 + jl)] * dist;
    }

    // ---- accumulators ----
    float acc[PPT][OUTD];
#pragma unroll
    for (int p = 0; p < PPT; ++p)
#pragma unroll
        for (int o = 0; o < OUTD; ++o) acc[p][o] = 0.f;

    // ---- mainloop over hidden dim ----
#pragma unroll 2
    for (int h = 0; h < HID; ++h) {
        const float sA = As[ti][h];
        const float bb = b1s[h];
        float h1v[PPT];
#pragma unroll
        for (int p = 0; p < PPT; ++p) {
            float pre = fmaf(wv[p], sA + Bs[h][tj + 32 * p], bb);
            h1v[p] = swish_f(pre);
        }
        const float4* wrow = (const float4*)(&W2Ts[h][0]);
#pragma unroll
        for (int oc = 0; oc < OUTD / 4; ++oc) {
            float4 wq = wrow[oc];             // uniform across warp -> LDS broadcast
#pragma unroll
            for (int p = 0; p < PPT; ++p) {
                acc[p][4 * oc + 0] = fmaf(h1v[p], wq.x, acc[p][4 * oc + 0]);
                acc[p][4 * oc + 1] = fmaf(h1v[p], wq.y, acc[p][4 * oc + 1]);
                acc[p][4 * oc + 2] = fmaf(h1v[p], wq.z, acc[p][4 * oc + 2]);
                acc[p][4 * oc + 3] = fmaf(h1v[p], wq.w, acc[p][4 * oc + 3]);
            }
        }
    }

    // ---- epilogue: +b2, swish, coalesced float4 stores ----
#pragma unroll
    for (int p = 0; p < PPT; ++p) {
        int j = j0 + tj + 32 * p;
        float4* outp = (float4*)(out + ((size_t)i * NN + j) * OUTD);
#pragma unroll
        for (int oc = 0; oc < OUTD / 4; ++oc) {
            float4 r;
            r.x = swish_f(acc[p][4 * oc + 0] + b2s[4 * oc + 0]);
            r.y = swish_f(acc[p][4 * oc + 1] + b2s[4 * oc + 1]);
            r.z = swish_f(acc[p][4 * oc + 2] + b2s[4 * oc + 2]);
            r.w = swish_f(acc[p][4 * oc + 3] + b2s[4 * oc + 3]);
            outp[oc] = r;
        }
    }
}

extern "C" void kernel_launch(void* const* d_in, const int* in_sizes, int n_in,
                              void* d_out, int out_size) {
    const float* Edges  = (const float*)d_in[0];
    const float* Coords = (const float*)d_in[1];
    const float* Emb    = (const float*)d_in[2];
    const float* W1     = (const float*)d_in[3];
    const float* b1     = (const float*)d_in[4];
    const float* W2     = (const float*)d_in[5];
    const float* b2     = (const float*)d_in[6];
    float* out = (float*)d_out;

    precompute_AB<<<(NN * HID + 255) / 256, 256>>>(Emb, W1);

    dim3 grid(NN / JTILE, NN / ITILE);   // (8, 256)
    fused_phi_kernel<<<grid, THREADS>>>(Edges, Coords, b1, W2, b2, out);
}

// round 10
// speedup vs baseline: 1.6332x; 1.6332x over previous
#include <cuda_runtime.h>
#include <cuda_bf16.h>
#include <stdint.h>
#include <math.h>

#define NN   1024
#define F    32
#define HID  64
#define OUTD 32
#define JT   128            // j-rows (MMA M) per tile
#define THREADS 128
#define NTILES  8192        // 1024 i * 8 j-tiles
#define GRID    1480

// SMEM: h1 hi/lo tiles, 128 rows x 64 bf16 (128B rows), SW128-style XOR swizzle
#define OFF_AHI 0
#define OFF_ALO 16384
#define SMEM_BYTES 32768

__device__ float g_A[NN * HID];   // A[i][h] = Emb[i,:] . W1[h, 0:F]
__device__ float g_B[NN * HID];   // B[j][h] = Emb[j,:] . W1[h, F:2F]

__global__ void precompute_AB(const float* __restrict__ Emb,
                              const float* __restrict__ W1) {
    int gid = blockIdx.x * blockDim.x + threadIdx.x;
    if (gid >= NN * HID) return;
    int i = gid >> 6;
    int h = gid & (HID - 1);
    const float* e  = Emb + i * F;
    const float* w1 = W1 + h * (2 * F);
    float a = 0.f, b = 0.f;
#pragma unroll
    for (int f = 0; f < F; ++f) {
        float ev = e[f];
        a = fmaf(ev, w1[f],     a);
        b = fmaf(ev, w1[F + f], b);
    }
    g_A[gid] = a;
    g_B[gid] = b;
}

__device__ __forceinline__ uint32_t smem_u32(const void* p) {
    uint32_t a;
    asm("{ .reg .u64 t; cvta.to.shared.u64 t, %1; cvt.u32.u64 %0, t; }"
        : "=r"(a) : "l"(p));
    return a;
}

// h1 swish: 1 MUFU via tanh.approx (error averaged by the GEMM reduction)
__device__ __forceinline__ float swish_h1(float x) {
    float xh = 0.5f * x;
    float t;
    asm("tanh.approx.f32 %0, %1;" : "=f"(t) : "f"(xh));
    return fmaf(xh, t, xh);          // x * (0.5*tanh(x/2) + 0.5)
}

// output swish: exact to ~2^-22 (elementwise-visible path)
__device__ __forceinline__ float swish_f(float x) {
    float e = __expf(-x);
    return x * __fdividef(1.0f, 1.0f + e);
}

__device__ __forceinline__ void ldsm_x4(uint32_t addr, uint32_t* r) {
    asm volatile("ldmatrix.sync.aligned.m8n8.x4.shared.b16 {%0,%1,%2,%3}, [%4];"
                 : "=r"(r[0]), "=r"(r[1]), "=r"(r[2]), "=r"(r[3]) : "r"(addr));
}

__device__ __forceinline__ void mma_bf16(float* d, const uint32_t* a,
                                         const uint32_t* b) {
    asm volatile(
        "mma.sync.aligned.m16n8k16.row.col.f32.bf16.bf16.f32 "
        "{%0,%1,%2,%3}, {%4,%5,%6,%7}, {%8,%9}, {%0,%1,%2,%3};"
        : "+f"(d[0]), "+f"(d[1]), "+f"(d[2]), "+f"(d[3])
        : "r"(a[0]), "r"(a[1]), "r"(a[2]), "r"(a[3]), "r"(b[0]), "r"(b[1]));
}

__global__ void __launch_bounds__(THREADS, 3)
phi_mma_kernel(const float* __restrict__ Edges,
               const float* __restrict__ Coords,
               const float* __restrict__ b1,
               const float* __restrict__ W2,     // (OUTD, HID) row-major
               const float* __restrict__ b2,
               float* __restrict__ out)          // (NN, NN, OUTD)
{
    __shared__ __align__(1024) unsigned char sbuf[SMEM_BYTES];
    __shared__ float ws[JT];

    const int tid   = threadIdx.x;
    const int lane  = tid & 31;
    const int wid   = tid >> 5;
    const int chunk = tid & 7;       // h-chunk for h1 writes
    const int rsub  = tid >> 3;      // row-within-pass: 0..15
    const uint32_t sb = smem_u32(sbuf);

    // ---- loop-invariant: W2 fragments (bf16 hi/lo) in registers ----
    // B frag for m16n8k16: lane holds {B[k][n],B[k+1][n]} pairs, contiguous in W2 rows.
    const int fn = lane >> 2;        // n within 8-wide ntile
    const int fk = (lane & 3) * 2;   // k base within 8-wide kblock
    uint32_t bh[4][4][2], bl[4][4][2];
#pragma unroll
    for (int nt = 0; nt < 4; ++nt) {
#pragma unroll
        for (int kt = 0; kt < 4; ++kt) {
            const float* wp = W2 + (8 * nt + fn) * HID + 16 * kt + fk;
#pragma unroll
            for (int hh = 0; hh < 2; ++hh) {
                float2 v = *(const float2*)(wp + 8 * hh);
                __nv_bfloat162 hi = __floats2bfloat162_rn(v.x, v.y);
                __nv_bfloat162 lo = __floats2bfloat162_rn(v.x - __low2float(hi),
                                                          v.y - __high2float(hi));
                bh[nt][kt][hh] = *(uint32_t*)&hi;
                bl[nt][kt][hh] = *(uint32_t*)&lo;
            }
        }
    }
    // b2 values this lane needs in the epilogue
    float2 b2v[4];
#pragma unroll
    for (int nt = 0; nt < 4; ++nt)
        b2v[nt] = *(const float2*)(b2 + 8 * nt + fk);

    // b1 chunk in registers (constant across tiles)
    const float4* b1p = (const float4*)(b1 + chunk * 8);
    const float4 b1a = b1p[0], b1b = b1p[1];

    for (int t = blockIdx.x; t < NTILES; t += GRID) {
        const int i  = t >> 3;
        const int j0 = (t & 7) * JT;

        // per-pair weight w = Edges * dist (one j per thread)
        const float cx = Coords[3 * i], cy = Coords[3 * i + 1], cz = Coords[3 * i + 2];
        {
            int j = j0 + tid;
            float dx = cx - Coords[3 * j];
            float dy = cy - Coords[3 * j + 1];
            float dz = cz - Coords[3 * j + 2];
            float sq = fmaf(dx, dx, fmaf(dy, dy, dz * dz));
            ws[tid] = Edges[(size_t)i * NN + j] * sqrtf(sq);
        }
        const float4* Ap = (const float4*)(g_A + i * HID + chunk * 8);
        const float4 a0 = Ap[0], a1 = Ap[1];
        __syncthreads();   // ws ready; prev tile's ldmatrix reads fully done

        // ---- h1 = swish(w*(A+B)+b1) -> bf16 hi/lo, swizzled SMEM ----
#pragma unroll 1
        for (int pass = 0; pass < 8; ++pass) {
            const int r = pass * 16 + rsub;
            const float w = ws[r];
            const float4* Bp = (const float4*)(g_B + (size_t)(j0 + r) * HID + chunk * 8);
            const float4 v0 = Bp[0], v1 = Bp[1];

            float f0 = swish_h1(fmaf(w, a0.x + v0.x, b1a.x));
            float f1 = swish_h1(fmaf(w, a0.y + v0.y, b1a.y));
            float f2 = swish_h1(fmaf(w, a0.z + v0.z, b1a.z));
            float f3 = swish_h1(fmaf(w, a0.w + v0.w, b1a.w));
            float f4 = swish_h1(fmaf(w, a1.x + v1.x, b1b.x));
            float f5 = swish_h1(fmaf(w, a1.y + v1.y, b1b.y));
            float f6 = swish_h1(fmaf(w, a1.z + v1.z, b1b.z));
            float f7 = swish_h1(fmaf(w, a1.w + v1.w, b1b.w));

            __nv_bfloat162 h01 = __floats2bfloat162_rn(f0, f1);
            __nv_bfloat162 h23 = __floats2bfloat162_rn(f2, f3);
            __nv_bfloat162 h45 = __floats2bfloat162_rn(f4, f5);
            __nv_bfloat162 h67 = __floats2bfloat162_rn(f6, f7);
            __nv_bfloat162 l01 = __floats2bfloat162_rn(f0 - __low2float(h01),
                                                       f1 - __high2float(h01));
            __nv_bfloat162 l23 = __floats2bfloat162_rn(f2 - __low2float(h23),
                                                       f3 - __high2float(h23));
            __nv_bfloat162 l45 = __floats2bfloat162_rn(f4 - __low2float(h45),
                                                       f5 - __high2float(h45));
            __nv_bfloat162 l67 = __floats2bfloat162_rn(f6 - __low2float(h67),
                                                       f7 - __high2float(h67));

            // row r, 16B chunk 'chunk', XOR-swizzled: conflict-free 16B stores
            const uint32_t sw = (uint32_t)(r * 128 + ((chunk ^ (r & 7)) << 4));
            uint4 uh, ul;
            uh.x = *(uint32_t*)&h01; uh.y = *(uint32_t*)&h23;
            uh.z = *(uint32_t*)&h45; uh.w = *(uint32_t*)&h67;
            ul.x = *(uint32_t*)&l01; ul.y = *(uint32_t*)&l23;
            ul.z = *(uint32_t*)&l45; ul.w = *(uint32_t*)&l67;
            *(uint4*)(sbuf + OFF_AHI + sw) = uh;
            *(uint4*)(sbuf + OFF_ALO + sw) = ul;
        }
        __syncthreads();   // h1 tiles visible to all warps

        // ---- warp-level bf16 MMA: D = Ahi.Bhi + Alo.Bhi + Ahi.Blo ----
        float d[2][4][4];
#pragma unroll
        for (int m = 0; m < 2; ++m)
#pragma unroll
            for (int nt = 0; nt < 4; ++nt)
#pragma unroll
                for (int q = 0; q < 4; ++q) d[m][nt][q] = 0.f;

        // ldmatrix lane->address: row = R0 + (lane&15), kblock = 2*kt + (lane>>4)
        const int lrow_off = lane & 15;
        const int lkb      = lane >> 4;
#pragma unroll
        for (int kt = 0; kt < 4; ++kt) {
            uint32_t ah[2][4], al[2][4];
#pragma unroll
            for (int m = 0; m < 2; ++m) {
                const int row = 32 * wid + 16 * m + lrow_off;
                const int kb  = 2 * kt + lkb;
                const uint32_t addr =
                    sb + (uint32_t)(row * 128 + ((kb ^ (row & 7)) << 4));
                ldsm_x4(addr + OFF_AHI, ah[m]);
                ldsm_x4(addr + OFF_ALO, al[m]);
            }
#pragma unroll
            for (int m = 0; m < 2; ++m)
#pragma unroll
                for (int nt = 0; nt < 4; ++nt) {
                    mma_bf16(d[m][nt], ah[m], bh[nt][kt]);
                    mma_bf16(d[m][nt], al[m], bh[nt][kt]);
                    mma_bf16(d[m][nt], ah[m], bl[nt][kt]);
                }
        }

        // ---- epilogue: +b2, swish, float2 stores ----
#pragma unroll
        for (int m = 0; m < 2; ++m) {
            const int jlo = j0 + 32 * wid + 16 * m + (lane >> 2);
            float* orow0 = out + ((size_t)i * NN + jlo) * OUTD;
            float* orow1 = orow0 + (size_t)8 * OUTD;   // row jlo + 8
#pragma unroll
            for (int nt = 0; nt < 4; ++nt) {
                const int o = 8 * nt + fk;
                float2 r0, r1;
                r0.x = swish_f(d[m][nt][0] + b2v[nt].x);
                r0.y = swish_f(d[m][nt][1] + b2v[nt].y);
                r1.x = swish_f(d[m][nt][2] + b2v[nt].x);
                r1.y = swish_f(d[m][nt][3] + b2v[nt].y);
                *(float2*)(orow0 + o) = r0;
                *(float2*)(orow1 + o) = r1;
            }
        }
    }
}

extern "C" void kernel_launch(void* const* d_in, const int* in_sizes, int n_in,
                              void* d_out, int out_size) {
    const float* Edges  = (const float*)d_in[0];
    const float* Coords = (const float*)d_in[1];
    const float* Emb    = (const float*)d_in[2];
    const float* W1     = (const float*)d_in[3];
    const float* b1     = (const float*)d_in[4];
    const float* W2     = (const float*)d_in[5];
    const float* b2     = (const float*)d_in[6];
    float* out = (float*)d_out;

    precompute_AB<<<(NN * HID + 255) / 256, 256>>>(Emb, W1);
    phi_mma_kernel<<<GRID, THREADS>>>(Edges, Coords, b1, W2, b2, out);
}

// round 11
// speedup vs baseline: 2.0510x; 1.2559x over previous
#include <cuda_runtime.h>
#include <cuda_bf16.h>
#include <stdint.h>
#include <math.h>

#define NN   1024
#define F    32
#define HID  64
#define OUTD 32
#define JT   128            // j-rows (MMA M) per tile
#define THREADS 128
#define NTILES  8192        // 1024 i * 8 j-tiles
#define GRID    1480

// SMEM: h1 hi/lo tiles (128 rows x 64 bf16, 128B rows, XOR swizzle) + W2 frags
#define OFF_AHI 0
#define OFF_ALO 16384
#define OFF_BH  32768       // W2 hi frags: [kt][nt][lane] uint2 -> 4KB
#define OFF_BL  36864       // W2 lo frags: 4KB
#define SMEM_BYTES 40960

__device__ float g_A[NN * HID];   // A[i][h] = Emb[i,:] . W1[h, 0:F]
__device__ float g_B[NN * HID];   // B[j][h] = Emb[j,:] . W1[h, F:2F]

__global__ void precompute_AB(const float* __restrict__ Emb,
                              const float* __restrict__ W1) {
    int gid = blockIdx.x * blockDim.x + threadIdx.x;
    if (gid >= NN * HID) return;
    int i = gid >> 6;
    int h = gid & (HID - 1);
    const float* e  = Emb + i * F;
    const float* w1 = W1 + h * (2 * F);
    float a = 0.f, b = 0.f;
#pragma unroll
    for (int f = 0; f < F; ++f) {
        float ev = e[f];
        a = fmaf(ev, w1[f],     a);
        b = fmaf(ev, w1[F + f], b);
    }
    g_A[gid] = a;
    g_B[gid] = b;
}

__device__ __forceinline__ uint32_t smem_u32(const void* p) {
    uint32_t a;
    asm("{ .reg .u64 t; cvta.to.shared.u64 t, %1; cvt.u32.u64 %0, t; }"
        : "=r"(a) : "l"(p));
    return a;
}

// h1 swish: 1 MUFU via tanh.approx (error averaged by the GEMM reduction)
__device__ __forceinline__ float swish_h1(float x) {
    float xh = 0.5f * x;
    float t;
    asm("tanh.approx.f32 %0, %1;" : "=f"(t) : "f"(xh));
    return fmaf(xh, t, xh);          // x * (0.5*tanh(x/2) + 0.5)
}

// output swish: exact to ~2^-22 (elementwise-visible path)
__device__ __forceinline__ float swish_f(float x) {
    float e = __expf(-x);
    return x * __fdividef(1.0f, 1.0f + e);
}

__device__ __forceinline__ void ldsm_x4(uint32_t addr, uint32_t* r) {
    asm volatile("ldmatrix.sync.aligned.m8n8.x4.shared.b16 {%0,%1,%2,%3}, [%4];"
                 : "=r"(r[0]), "=r"(r[1]), "=r"(r[2]), "=r"(r[3]) : "r"(addr));
}

__device__ __forceinline__ void mma_bf16(float* d, const uint32_t* a,
                                         uint32_t b0, uint32_t b1) {
    asm volatile(
        "mma.sync.aligned.m16n8k16.row.col.f32.bf16.bf16.f32 "
        "{%0,%1,%2,%3}, {%4,%5,%6,%7}, {%8,%9}, {%0,%1,%2,%3};"
        : "+f"(d[0]), "+f"(d[1]), "+f"(d[2]), "+f"(d[3])
        : "r"(a[0]), "r"(a[1]), "r"(a[2]), "r"(a[3]), "r"(b0), "r"(b1));
}

__global__ void __launch_bounds__(THREADS, 5)
phi_mma_kernel(const float* __restrict__ Edges,
               const float* __restrict__ Coords,
               const float* __restrict__ b1,
               const float* __restrict__ W2,     // (OUTD, HID) row-major
               const float* __restrict__ b2,
               float* __restrict__ out)          // (NN, NN, OUTD)
{
    __shared__ __align__(1024) unsigned char sbuf[SMEM_BYTES];
    __shared__ float ws[JT];

    const int tid   = threadIdx.x;
    const int lane  = tid & 31;
    const int wid   = tid >> 5;
    const int chunk = tid & 7;       // h-chunk for h1 writes
    const int rsub  = tid >> 3;      // row-within-pass: 0..15
    const uint32_t sb = smem_u32(sbuf);

    // ---- loop-invariant W2 fragments -> SMEM (bf16 hi/lo, per-lane layout) ----
    // frag layout for m16n8k16 B: lane holds {B[k][n],B[k+1][n]} pairs.
    const int fn = lane >> 2;        // n within 8-wide ntile
    const int fk = (lane & 3) * 2;   // k base within 8-wide kblock
    if (wid == 0) {
#pragma unroll
        for (int nt = 0; nt < 4; ++nt) {
#pragma unroll
            for (int kt = 0; kt < 4; ++kt) {
                const float* wp = W2 + (8 * nt + fn) * HID + 16 * kt + fk;
                uint2 uh, ul;
                uint32_t* uhp = &uh.x;
                uint32_t* ulp = &ul.x;
#pragma unroll
                for (int hh = 0; hh < 2; ++hh) {
                    float2 v = *(const float2*)(wp + 8 * hh);
                    __nv_bfloat162 hi = __floats2bfloat162_rn(v.x, v.y);
                    __nv_bfloat162 lo = __floats2bfloat162_rn(v.x - __low2float(hi),
                                                              v.y - __high2float(hi));
                    uhp[hh] = *(uint32_t*)&hi;
                    ulp[hh] = *(uint32_t*)&lo;
                }
                const uint32_t fo = (uint32_t)(((kt * 4 + nt) * 32 + lane) * 8);
                *(uint2*)(sbuf + OFF_BH + fo) = uh;
                *(uint2*)(sbuf + OFF_BL + fo) = ul;
            }
        }
    }

    // b2 values this lane needs in the epilogue
    float2 b2v[4];
#pragma unroll
    for (int nt = 0; nt < 4; ++nt)
        b2v[nt] = *(const float2*)(b2 + 8 * nt + fk);

    // b1 chunk in registers (constant across tiles)
    const float4* b1p = (const float4*)(b1 + chunk * 8);
    const float4 b1a = b1p[0], b1b = b1p[1];
    __syncthreads();

    for (int t = blockIdx.x; t < NTILES; t += GRID) {
        const int i  = t >> 3;
        const int j0 = (t & 7) * JT;

        // per-pair weight w = Edges * dist (one j per thread)
        const float cx = Coords[3 * i], cy = Coords[3 * i + 1], cz = Coords[3 * i + 2];
        {
            int j = j0 + tid;
            float dx = cx - Coords[3 * j];
            float dy = cy - Coords[3 * j + 1];
            float dz = cz - Coords[3 * j + 2];
            float sq = fmaf(dx, dx, fmaf(dy, dy, dz * dz));
            ws[tid] = Edges[(size_t)i * NN + j] * sqrtf(sq);
        }
        const float4* Ap = (const float4*)(g_A + i * HID + chunk * 8);
        const float4 a0 = Ap[0], a1 = Ap[1];
        __syncthreads();   // ws ready; prev tile's ldmatrix reads fully done

        // ---- h1 = swish(w*(A+B)+b1) -> bf16 hi/lo, swizzled SMEM ----
        // unroll 2: doubles outstanding g_B loads (hide L2 latency)
#pragma unroll 2
        for (int pass = 0; pass < 8; ++pass) {
            const int r = pass * 16 + rsub;
            const float w = ws[r];
            const float4* Bp = (const float4*)(g_B + (size_t)(j0 + r) * HID + chunk * 8);
            const float4 v0 = Bp[0], v1 = Bp[1];

            float f0 = swish_h1(fmaf(w, a0.x + v0.x, b1a.x));
            float f1 = swish_h1(fmaf(w, a0.y + v0.y, b1a.y));
            float f2 = swish_h1(fmaf(w, a0.z + v0.z, b1a.z));
            float f3 = swish_h1(fmaf(w, a0.w + v0.w, b1a.w));
            float f4 = swish_h1(fmaf(w, a1.x + v1.x, b1b.x));
            float f5 = swish_h1(fmaf(w, a1.y + v1.y, b1b.y));
            float f6 = swish_h1(fmaf(w, a1.z + v1.z, b1b.z));
            float f7 = swish_h1(fmaf(w, a1.w + v1.w, b1b.w));

            __nv_bfloat162 h01 = __floats2bfloat162_rn(f0, f1);
            __nv_bfloat162 h23 = __floats2bfloat162_rn(f2, f3);
            __nv_bfloat162 h45 = __floats2bfloat162_rn(f4, f5);
            __nv_bfloat162 h67 = __floats2bfloat162_rn(f6, f7);
            __nv_bfloat162 l01 = __floats2bfloat162_rn(f0 - __low2float(h01),
                                                       f1 - __high2float(h01));
            __nv_bfloat162 l23 = __floats2bfloat162_rn(f2 - __low2float(h23),
                                                       f3 - __high2float(h23));
            __nv_bfloat162 l45 = __floats2bfloat162_rn(f4 - __low2float(h45),
                                                       f5 - __high2float(h45));
            __nv_bfloat162 l67 = __floats2bfloat162_rn(f6 - __low2float(h67),
                                                       f7 - __high2float(h67));

            // row r, 16B chunk 'chunk', XOR-swizzled: conflict-free 16B stores
            const uint32_t sw = (uint32_t)(r * 128 + ((chunk ^ (r & 7)) << 4));
            uint4 uh, ul;
            uh.x = *(uint32_t*)&h01; uh.y = *(uint32_t*)&h23;
            uh.z = *(uint32_t*)&h45; uh.w = *(uint32_t*)&h67;
            ul.x = *(uint32_t*)&l01; ul.y = *(uint32_t*)&l23;
            ul.z = *(uint32_t*)&l45; ul.w = *(uint32_t*)&l67;
            *(uint4*)(sbuf + OFF_AHI + sw) = uh;
            *(uint4*)(sbuf + OFF_ALO + sw) = ul;
        }
        __syncthreads();   // h1 tiles visible to all warps

        // ---- warp-level bf16 MMA: D = Ahi.Bhi + Alo.Bhi + Ahi.Blo ----
        float d[2][4][4];
#pragma unroll
        for (int m = 0; m < 2; ++m)
#pragma unroll
            for (int nt = 0; nt < 4; ++nt)
#pragma unroll
                for (int q = 0; q < 4; ++q) d[m][nt][q] = 0.f;

        // ldmatrix lane->address: row = R0 + (lane&15), kblock = 2*kt + (lane>>4)
        const int lrow_off = lane & 15;
        const int lkb      = lane >> 4;
#pragma unroll
        for (int kt = 0; kt < 4; ++kt) {
            uint32_t ah[2][4], al[2][4];
#pragma unroll
            for (int m = 0; m < 2; ++m) {
                const int row = 32 * wid + 16 * m + lrow_off;
                const int kb  = 2 * kt + lkb;
                const uint32_t addr =
                    sb + (uint32_t)(row * 128 + ((kb ^ (row & 7)) << 4));
                ldsm_x4(addr + OFF_AHI, ah[m]);
                ldsm_x4(addr + OFF_ALO, al[m]);
            }
            // W2 frags for this kt from SMEM (conflict-free LDS.64)
            uint2 bhv[4], blv[4];
#pragma unroll
            for (int nt = 0; nt < 4; ++nt) {
                const uint32_t fo = (uint32_t)(((kt * 4 + nt) * 32 + lane) * 8);
                bhv[nt] = *(const uint2*)(sbuf + OFF_BH + fo);
                blv[nt] = *(const uint2*)(sbuf + OFF_BL + fo);
            }
#pragma unroll
            for (int m = 0; m < 2; ++m)
#pragma unroll
                for (int nt = 0; nt < 4; ++nt) {
                    mma_bf16(d[m][nt], ah[m], bhv[nt].x, bhv[nt].y);
                    mma_bf16(d[m][nt], al[m], bhv[nt].x, bhv[nt].y);
                    mma_bf16(d[m][nt], ah[m], blv[nt].x, blv[nt].y);
                }
        }

        // ---- epilogue: +b2, swish, float2 stores ----
#pragma unroll
        for (int m = 0; m < 2; ++m) {
            const int jlo = j0 + 32 * wid + 16 * m + (lane >> 2);
            float* orow0 = out + ((size_t)i * NN + jlo) * OUTD;
            float* orow1 = orow0 + (size_t)8 * OUTD;   // row jlo + 8
#pragma unroll
            for (int nt = 0; nt < 4; ++nt) {
                const int o = 8 * nt + fk;
                float2 r0, r1;
                r0.x = swish_f(d[m][nt][0] + b2v[nt].x);
                r0.y = swish_f(d[m][nt][1] + b2v[nt].y);
                r1.x = swish_f(d[m][nt][2] + b2v[nt].x);
                r1.y = swish_f(d[m][nt][3] + b2v[nt].y);
                *(float2*)(orow0 + o) = r0;
                *(float2*)(orow1 + o) = r1;
            }
        }
    }
}

extern "C" void kernel_launch(void* const* d_in, const int* in_sizes, int n_in,
                              void* d_out, int out_size) {
    const float* Edges  = (const float*)d_in[0];
    const float* Coords = (const float*)d_in[1];
    const float* Emb    = (const float*)d_in[2];
    const float* W1     = (const float*)d_in[3];
    const float* b1     = (const float*)d_in[4];
    const float* W2     = (const float*)d_in[5];
    const float* b2     = (const float*)d_in[6];
    float* out = (float*)d_out;

    precompute_AB<<<(NN * HID + 255) / 256, 256>>>(Emb, W1);
    phi_mma_kernel<<<GRID, THREADS>>>(Edges, Coords, b1, W2, b2, out);
}

// round 16
// speedup vs baseline: 2.1899x; 1.0677x over previous
#include <cuda_runtime.h>
#include <cuda_bf16.h>
#include <cuda_fp16.h>
#include <stdint.h>
#include <math.h>

#define NN   1024
#define F    32
#define HID  64
#define OUTD 32
#define JT   128            // j-rows (MMA M) per tile
#define THREADS 128
#define NTILES  8192        // 1024 i * 8 j-tiles
#define GRID    1480

// SMEM: h1 fp16 tile (128 rows x 64 fp16 = 128B rows, XOR swizzle) + W2 frags
#define OFF_AHI 0
#define OFF_BF  16384       // W2 frags: [kt][nt][lane] uint4 {hi0,hi1,lo0,lo1} -> 8KB
#define SMEM_BYTES 24576

#define W2SCALE     64.0f
#define W2SCALE_INV 0.015625f

__device__ float g_A[NN * HID];   // A[i][h] = Emb[i,:] . W1[h, 0:F]
__device__ float g_B[NN * HID];   // B[j][h] = Emb[j,:] . W1[h, F:2F]

__global__ void precompute_AB(const float* __restrict__ Emb,
                              const float* __restrict__ W1) {
    int gid = blockIdx.x * blockDim.x + threadIdx.x;
    if (gid >= NN * HID) return;
    int i = gid >> 6;
    int h = gid & (HID - 1);
    const float* e  = Emb + i * F;
    const float* w1 = W1 + h * (2 * F);
    float a = 0.f, b = 0.f;
#pragma unroll
    for (int f = 0; f < F; ++f) {
        float ev = e[f];
        a = fmaf(ev, w1[f],     a);
        b = fmaf(ev, w1[F + f], b);
    }
    g_A[gid] = a;
    g_B[gid] = b;
}

__device__ __forceinline__ uint32_t smem_u32(const void* p) {
    uint32_t a;
    asm("{ .reg .u64 t; cvta.to.shared.u64 t, %1; cvt.u32.u64 %0, t; }"
        : "=r"(a) : "l"(p));
    return a;
}

// h1 swish: 1 MUFU via tanh.approx (error averaged by the GEMM reduction)
__device__ __forceinline__ float swish_h1(float x) {
    float xh = 0.5f * x;
    float t;
    asm("tanh.approx.f32 %0, %1;" : "=f"(t) : "f"(xh));
    return fmaf(xh, t, xh);          // x * (0.5*tanh(x/2) + 0.5)
}

// output swish: exact to ~2^-22 (elementwise-visible path)
__device__ __forceinline__ float swish_f(float x) {
    float e = __expf(-x);
    return x * __fdividef(1.0f, 1.0f + e);
}

__device__ __forceinline__ void ldsm_x4(uint32_t addr, uint32_t* r) {
    asm volatile("ldmatrix.sync.aligned.m8n8.x4.shared.b16 {%0,%1,%2,%3}, [%4];"
                 : "=r"(r[0]), "=r"(r[1]), "=r"(r[2]), "=r"(r[3]) : "r"(addr));
}

__device__ __forceinline__ void mma_fp16(float* d, const uint32_t* a,
                                         uint32_t b0, uint32_t b1) {
    asm volatile(
        "mma.sync.aligned.m16n8k16.row.col.f32.f16.f16.f32 "
        "{%0,%1,%2,%3}, {%4,%5,%6,%7}, {%8,%9}, {%0,%1,%2,%3};"
        : "+f"(d[0]), "+f"(d[1]), "+f"(d[2]), "+f"(d[3])
        : "r"(a[0]), "r"(a[1]), "r"(a[2]), "r"(a[3]), "r"(b0), "r"(b1));
}

__global__ void __launch_bounds__(THREADS, 6)
phi_mma_kernel(const float* __restrict__ Edges,
               const float* __restrict__ Coords,
               const float* __restrict__ b1,
               const float* __restrict__ W2,     // (OUTD, HID) row-major
               const float* __restrict__ b2,
               float* __restrict__ out)          // (NN, NN, OUTD)
{
    __shared__ __align__(1024) unsigned char sbuf[SMEM_BYTES];
    __shared__ float ws[JT];

    const int tid   = threadIdx.x;
    const int lane  = tid & 31;
    const int wid   = tid >> 5;
    const int chunk = tid & 7;       // h-chunk for h1 writes
    const int rsub  = tid >> 3;      // row-within-pass: 0..15
    const uint32_t sb = smem_u32(sbuf);

    // ---- loop-invariant W2 fragments -> SMEM (fp16 hi/lo of 64*W2) ----
    // frag layout for m16n8k16 B: lane holds {B[k][n],B[k+1][n]} pairs.
    const int fn = lane >> 2;        // n within 8-wide ntile
    const int fk = (lane & 3) * 2;   // k base within 8-wide kblock
    if (wid == 0) {
#pragma unroll
        for (int nt = 0; nt < 4; ++nt) {
#pragma unroll
            for (int kt = 0; kt < 4; ++kt) {
                const float* wp = W2 + (8 * nt + fn) * HID + 16 * kt + fk;
                uint4 uf;
                uint32_t* up = &uf.x;
#pragma unroll
                for (int hh = 0; hh < 2; ++hh) {
                    float2 v = *(const float2*)(wp + 8 * hh);
                    float sx = v.x * W2SCALE, sy = v.y * W2SCALE;
                    __half2 hi = __floats2half2_rn(sx, sy);
                    __half2 lo = __floats2half2_rn(sx - __low2float(hi),
                                                   sy - __high2float(hi));
                    up[hh]     = *(uint32_t*)&hi;   // .x, .y  = hi0, hi1
                    up[2 + hh] = *(uint32_t*)&lo;   // .z, .w  = lo0, lo1
                }
                const uint32_t fo = (uint32_t)(((kt * 4 + nt) * 32 + lane) * 16);
                *(uint4*)(sbuf + OFF_BF + fo) = uf;
            }
        }
    }

    // b2 values this lane needs in the epilogue
    float2 b2v[4];
#pragma unroll
    for (int nt = 0; nt < 4; ++nt)
        b2v[nt] = *(const float2*)(b2 + 8 * nt + fk);

    // b1 chunk in registers (constant across tiles)
    const float4* b1p = (const float4*)(b1 + chunk * 8);
    const float4 b1a = b1p[0], b1b = b1p[1];
    __syncthreads();

    for (int t = blockIdx.x; t < NTILES; t += GRID) {
        const int i  = t >> 3;
        const int j0 = (t & 7) * JT;

        // per-pair weight w = Edges * dist (one j per thread)
        const float cx = Coords[3 * i], cy = Coords[3 * i + 1], cz = Coords[3 * i + 2];
        {
            int j = j0 + tid;
            float dx = cx - Coords[3 * j];
            float dy = cy - Coords[3 * j + 1];
            float dz = cz - Coords[3 * j + 2];
            float sq = fmaf(dx, dx, fmaf(dy, dy, dz * dz));
            ws[tid] = Edges[(size_t)i * NN + j] * sqrtf(sq);
        }
        const float4* Ap = (const float4*)(g_A + i * HID + chunk * 8);
        const float4 a0 = Ap[0], a1 = Ap[1];
        __syncthreads();   // ws ready; prev tile's ldmatrix reads fully done

        // ---- h1 = swish(w*(A+B)+b1) -> fp16, swizzled SMEM ----
        // unroll 2: doubles outstanding g_B loads (hide L2 latency)
#pragma unroll 2
        for (int pass = 0; pass < 8; ++pass) {
            const int r = pass * 16 + rsub;
            const float w = ws[r];
            const float4* Bp = (const float4*)(g_B + (size_t)(j0 + r) * HID + chunk * 8);
            const float4 v0 = Bp[0], v1 = Bp[1];

            float f0 = swish_h1(fmaf(w, a0.x + v0.x, b1a.x));
            float f1 = swish_h1(fmaf(w, a0.y + v0.y, b1a.y));
            float f2 = swish_h1(fmaf(w, a0.z + v0.z, b1a.z));
            float f3 = swish_h1(fmaf(w, a0.w + v0.w, b1a.w));
            float f4 = swish_h1(fmaf(w, a1.x + v1.x, b1b.x));
            float f5 = swish_h1(fmaf(w, a1.y + v1.y, b1b.y));
            float f6 = swish_h1(fmaf(w, a1.z + v1.z, b1b.z));
            float f7 = swish_h1(fmaf(w, a1.w + v1.w, b1b.w));

            __half2 h01 = __floats2half2_rn(f0, f1);
            __half2 h23 = __floats2half2_rn(f2, f3);
            __half2 h45 = __floats2half2_rn(f4, f5);
            __half2 h67 = __floats2half2_rn(f6, f7);

            // row r, 16B chunk 'chunk', XOR-swizzled: conflict-free 16B stores
            const uint32_t sw = (uint32_t)(r * 128 + ((chunk ^ (r & 7)) << 4));
            uint4 uh;
            uh.x = *(uint32_t*)&h01; uh.y = *(uint32_t*)&h23;
            uh.z = *(uint32_t*)&h45; uh.w = *(uint32_t*)&h67;
            *(uint4*)(sbuf + OFF_AHI + sw) = uh;
        }
        __syncthreads();   // h1 tile visible to all warps

        // ---- warp-level fp16 MMA: D = Ahi.Bhi + Ahi.Blo  ( = h1 . 64*W2 ) ----
        float d[2][4][4];
#pragma unroll
        for (int m = 0; m < 2; ++m)
#pragma unroll
            for (int nt = 0; nt < 4; ++nt)
#pragma unroll
                for (int q = 0; q < 4; ++q) d[m][nt][q] = 0.f;

        // ldmatrix lane->address: row = R0 + (lane&15), kblock = 2*kt + (lane>>4)
        const int lrow_off = lane & 15;
        const int lkb      = lane >> 4;
#pragma unroll
        for (int kt = 0; kt < 4; ++kt) {
            uint32_t ah[2][4];
#pragma unroll
            for (int m = 0; m < 2; ++m) {
                const int row = 32 * wid + 16 * m + lrow_off;
                const int kb  = 2 * kt + lkb;
                const uint32_t addr =
                    sb + (uint32_t)(row * 128 + ((kb ^ (row & 7)) << 4));
                ldsm_x4(addr + OFF_AHI, ah[m]);
            }
            // W2 frags for this kt from SMEM (LDS.128, conflict-free)
            uint4 bf[4];
#pragma unroll
            for (int nt = 0; nt < 4; ++nt) {
                const uint32_t fo = (uint32_t)(((kt * 4 + nt) * 32 + lane) * 16);
                bf[nt] = *(const uint4*)(sbuf + OFF_BF + fo);
            }
#pragma unroll
            for (int m = 0; m < 2; ++m)
#pragma unroll
                for (int nt = 0; nt < 4; ++nt) {
                    mma_fp16(d[m][nt], ah[m], bf[nt].x, bf[nt].y);   // Ahi.Bhi
                    mma_fp16(d[m][nt], ah[m], bf[nt].z, bf[nt].w);   // Ahi.Blo
                }
        }

        // ---- epilogue: d/64 + b2, swish, float2 stores ----
#pragma unroll
        for (int m = 0; m < 2; ++m) {
            const int jlo = j0 + 32 * wid + 16 * m + (lane >> 2);
            float* orow0 = out + ((size_t)i * NN + jlo) * OUTD;
            float* orow1 = orow0 + (size_t)8 * OUTD;   // row jlo + 8
#pragma unroll
            for (int nt = 0; nt < 4; ++nt) {
                const int o = 8 * nt + fk;
                float2 r0, r1;
                r0.x = swish_f(fmaf(d[m][nt][0], W2SCALE_INV, b2v[nt].x));
                r0.y = swish_f(fmaf(d[m][nt][1], W2SCALE_INV, b2v[nt].y));
                r1.x = swish_f(fmaf(d[m][nt][2], W2SCALE_INV, b2v[nt].x));
                r1.y = swish_f(fmaf(d[m][nt][3], W2SCALE_INV, b2v[nt].y));
                *(float2*)(orow0 + o) = r0;
                *(float2*)(orow1 + o) = r1;
            }
        }
    }
}

extern "C" void kernel_launch(void* const* d_in, const int* in_sizes, int n_in,
                              void* d_out, int out_size) {
    const float* Edges  = (const float*)d_in[0];
    const float* Coords = (const float*)d_in[1];
    const float* Emb    = (const float*)d_in[2];
    const float* W1     = (const float*)d_in[3];
    const float* b1     = (const float*)d_in[4];
    const float* W2     = (const float*)d_in[5];
    const float* b2     = (const float*)d_in[6];
    float* out = (float*)d_out;

    precompute_AB<<<(NN * HID + 255) / 256, 256>>>(Emb, W1);
    phi_mma_kernel<<<GRID, THREADS>>>(Edges, Coords, b1, W2, b2, out);
}

// round 17
// speedup vs baseline: 2.9731x; 1.3577x over previous
#include <cuda_runtime.h>
#include <cuda_fp16.h>
#include <stdint.h>
#include <math.h>

#define NN   1024
#define F    32
#define HID  64
#define OUTD 32
#define JT   128            // j-rows (MMA M) per tile
#define THREADS 128
#define NTILES  8192        // 1024 i * 8 j-tiles
#define GRID    1480

// SMEM: h1 fp16 tile (128 rows x 64 fp16 = 128B rows, XOR swizzle) + W2 frags
#define OFF_AHI 0
#define OFF_BF  16384       // W2 frags: [kt][nt][lane] uint2 {hi0,hi1} -> 4KB
#define SMEM_BYTES 20480

#define W2SCALE     64.0f
#define W2SCALE_INV 0.015625f

__device__ float g_A[NN * HID];   // A[i][h] = Emb[i,:] . W1[h, 0:F]
__device__ float g_B[NN * HID];   // B[j][h] = Emb[j,:] . W1[h, F:2F]

// ---- precompute v2: W1 staged in SMEM (coalesced + conflict-free) ----
__global__ void __launch_bounds__(512) precompute_AB(const float* __restrict__ Emb,
                                                     const float* __restrict__ W1) {
    __shared__ float W1s[HID][65];     // pad 65: bank = (h+f)%32, conflict-free
    __shared__ float Embs[8][33];
    const int tid = threadIdx.x;
    // W1: 64x64 floats, coalesced scalar loads
#pragma unroll
    for (int k = 0; k < 8; ++k) {
        int idx = tid + 512 * k;
        W1s[idx >> 6][idx & 63] = W1[idx];
    }
    if (tid < 256) {
        int r = tid >> 5, f = tid & 31;
        Embs[r][f] = Emb[(blockIdx.x * 8 + r) * F + f];
    }
    __syncthreads();
    const int il = tid >> 6;           // i within block (0..7)
    const int h  = tid & 63;
    float a = 0.f, b = 0.f;
#pragma unroll
    for (int f = 0; f < F; ++f) {
        float e = Embs[il][f];
        a = fmaf(e, W1s[h][f],     a);
        b = fmaf(e, W1s[h][F + f], b);
    }
    int gid = blockIdx.x * 512 + tid;  // = (8*bx+il)*64 + h
    g_A[gid] = a;
    g_B[gid] = b;
}

__device__ __forceinline__ uint32_t smem_u32(const void* p) {
    uint32_t a;
    asm("{ .reg .u64 t; cvta.to.shared.u64 t, %1; cvt.u32.u64 %0, t; }"
        : "=r"(a) : "l"(p));
    return a;
}

// h1 swish: 1 MUFU via tanh.approx (error averaged by the GEMM reduction)
__device__ __forceinline__ float swish_h1(float x) {
    float xh = 0.5f * x;
    float t;
    asm("tanh.approx.f32 %0, %1;" : "=f"(t) : "f"(xh));
    return fmaf(xh, t, xh);          // x * (0.5*tanh(x/2) + 0.5)
}

// output swish: exact to ~2^-22 (elementwise-visible path)
__device__ __forceinline__ float swish_f(float x) {
    float e = __expf(-x);
    return x * __fdividef(1.0f, 1.0f + e);
}

__device__ __forceinline__ void ldsm_x4(uint32_t addr, uint32_t* r) {
    asm volatile("ldmatrix.sync.aligned.m8n8.x4.shared.b16 {%0,%1,%2,%3}, [%4];"
                 : "=r"(r[0]), "=r"(r[1]), "=r"(r[2]), "=r"(r[3]) : "r"(addr));
}

__device__ __forceinline__ void mma_fp16(float* d, const uint32_t* a,
                                         uint32_t b0, uint32_t b1) {
    asm volatile(
        "mma.sync.aligned.m16n8k16.row.col.f32.f16.f16.f32 "
        "{%0,%1,%2,%3}, {%4,%5,%6,%7}, {%8,%9}, {%0,%1,%2,%3};"
        : "+f"(d[0]), "+f"(d[1]), "+f"(d[2]), "+f"(d[3])
        : "r"(a[0]), "r"(a[1]), "r"(a[2]), "r"(a[3]), "r"(b0), "r"(b1));
}

__global__ void __launch_bounds__(THREADS, 6)
phi_mma_kernel(const float* __restrict__ Edges,
               const float* __restrict__ Coords,
               const float* __restrict__ b1,
               const float* __restrict__ W2,     // (OUTD, HID) row-major
               const float* __restrict__ b2,
               float* __restrict__ out)          // (NN, NN, OUTD)
{
    __shared__ __align__(1024) unsigned char sbuf[SMEM_BYTES];

    const int tid   = threadIdx.x;
    const int lane  = tid & 31;
    const int wid   = tid >> 5;
    const int chunk = lane & 7;      // h-chunk for h1 writes
    const int rsub4 = lane >> 3;     // row-within-pass: 0..3
    const uint32_t sb = smem_u32(sbuf);

    // ---- loop-invariant W2 fragments -> SMEM (fp16 of 64*W2, single term) ----
    // frag layout for m16n8k16 B: lane holds {B[k][n],B[k+1][n]} pairs.
    const int fn = lane >> 2;        // n within 8-wide ntile
    const int fk = (lane & 3) * 2;   // k base within 8-wide kblock
    if (wid == 0) {
#pragma unroll
        for (int nt = 0; nt < 4; ++nt) {
#pragma unroll
            for (int kt = 0; kt < 4; ++kt) {
                const float* wp = W2 + (8 * nt + fn) * HID + 16 * kt + fk;
                uint2 uf;
                uint32_t* up = &uf.x;
#pragma unroll
                for (int hh = 0; hh < 2; ++hh) {
                    float2 v = *(const float2*)(wp + 8 * hh);
                    __half2 hi = __floats2half2_rn(v.x * W2SCALE, v.y * W2SCALE);
                    up[hh] = *(uint32_t*)&hi;
                }
                const uint32_t fo = (uint32_t)(((kt * 4 + nt) * 32 + lane) * 8);
                *(uint2*)(sbuf + OFF_BF + fo) = uf;
            }
        }
    }

    // b2 values this lane needs in the epilogue
    float2 b2v[4];
#pragma unroll
    for (int nt = 0; nt < 4; ++nt)
        b2v[nt] = *(const float2*)(b2 + 8 * nt + fk);

    // b1 chunk in registers (constant across tiles)
    const float4* b1p = (const float4*)(b1 + chunk * 8);
    const float4 b1a = b1p[0], b1b = b1p[1];
    __syncthreads();   // frags visible; after this, NO block barriers at all

    for (int t = blockIdx.x; t < NTILES; t += GRID) {
        const int i  = t >> 3;
        const int j0 = (t & 7) * JT;

        // per-pair weight w = Edges * dist; lane owns row 32*wid + lane
        const float cx = Coords[3 * i], cy = Coords[3 * i + 1], cz = Coords[3 * i + 2];
        float wv;
        {
            int j = j0 + 32 * wid + lane;
            float dx = cx - Coords[3 * j];
            float dy = cy - Coords[3 * j + 1];
            float dz = cz - Coords[3 * j + 2];
            float sq = fmaf(dx, dx, fmaf(dy, dy, dz * dz));
            wv = Edges[(size_t)i * NN + j] * sqrtf(sq);
        }
        const float4* Ap = (const float4*)(g_A + i * HID + chunk * 8);
        const float4 a0 = Ap[0], a1 = Ap[1];

        // ---- h1 = swish(w*(A+B)+b1) -> fp16, warp-private swizzled rows ----
#pragma unroll 2
        for (int pass = 0; pass < 8; ++pass) {
            const int rl  = pass * 4 + rsub4;        // 0..31 within warp
            const int row = 32 * wid + rl;           // tile row
            const float w = __shfl_sync(0xffffffffu, wv, rl);
            const float4* Bp = (const float4*)(g_B + (size_t)(j0 + row) * HID + chunk * 8);
            const float4 v0 = Bp[0], v1 = Bp[1];

            float f0 = swish_h1(fmaf(w, a0.x + v0.x, b1a.x));
            float f1 = swish_h1(fmaf(w, a0.y + v0.y, b1a.y));
            float f2 = swish_h1(fmaf(w, a0.z + v0.z, b1a.z));
            float f3 = swish_h1(fmaf(w, a0.w + v0.w, b1a.w));
            float f4 = swish_h1(fmaf(w, a1.x + v1.x, b1b.x));
            float f5 = swish_h1(fmaf(w, a1.y + v1.y, b1b.y));
            float f6 = swish_h1(fmaf(w, a1.z + v1.z, b1b.z));
            float f7 = swish_h1(fmaf(w, a1.w + v1.w, b1b.w));

            __half2 h01 = __floats2half2_rn(f0, f1);
            __half2 h23 = __floats2half2_rn(f2, f3);
            __half2 h45 = __floats2half2_rn(f4, f5);
            __half2 h67 = __floats2half2_rn(f6, f7);

            // row, 16B chunk, XOR-swizzled: 8 lanes cover one 128B row
            const uint32_t sw = (uint32_t)(row * 128 + ((chunk ^ (row & 7)) << 4));
            uint4 uh;
            uh.x = *(uint32_t*)&h01; uh.y = *(uint32_t*)&h23;
            uh.z = *(uint32_t*)&h45; uh.w = *(uint32_t*)&h67;
            *(uint4*)(sbuf + OFF_AHI + sw) = uh;
        }
        __syncwarp();   // warp-private tile: own STS visible to own ldmatrix

        // ---- warp-level fp16 MMA: D = Ahi . fp16(64*W2) ----
        float d[2][4][4];
#pragma unroll
        for (int m = 0; m < 2; ++m)
#pragma unroll
            for (int nt = 0; nt < 4; ++nt)
#pragma unroll
                for (int q = 0; q < 4; ++q) d[m][nt][q] = 0.f;

        const int lrow_off = lane & 15;
        const int lkb      = lane >> 4;
#pragma unroll
        for (int kt = 0; kt < 4; ++kt) {
            uint32_t ah[2][4];
#pragma unroll
            for (int m = 0; m < 2; ++m) {
                const int row = 32 * wid + 16 * m + lrow_off;
                const int kb  = 2 * kt + lkb;
                const uint32_t addr =
                    sb + (uint32_t)(row * 128 + ((kb ^ (row & 7)) << 4));
                ldsm_x4(addr + OFF_AHI, ah[m]);
            }
            uint2 bf[4];
#pragma unroll
            for (int nt = 0; nt < 4; ++nt) {
                const uint32_t fo = (uint32_t)(((kt * 4 + nt) * 32 + lane) * 8);
                bf[nt] = *(const uint2*)(sbuf + OFF_BF + fo);
            }
#pragma unroll
            for (int m = 0; m < 2; ++m)
#pragma unroll
                for (int nt = 0; nt < 4; ++nt)
                    mma_fp16(d[m][nt], ah[m], bf[nt].x, bf[nt].y);
        }
        __syncwarp();   // ldmatrix reads done before next tile's STS overwrite

        // ---- epilogue: d/64 + b2, swish, float2 stores ----
#pragma unroll
        for (int m = 0; m < 2; ++m) {
            const int jlo = j0 + 32 * wid + 16 * m + (lane >> 2);
            float* orow0 = out + ((size_t)i * NN + jlo) * OUTD;
            float* orow1 = orow0 + (size_t)8 * OUTD;   // row jlo + 8
#pragma unroll
            for (int nt = 0; nt < 4; ++nt) {
                const int o = 8 * nt + fk;
                float2 r0, r1;
                r0.x = swish_f(fmaf(d[m][nt][0], W2SCALE_INV, b2v[nt].x));
                r0.y = swish_f(fmaf(d[m][nt][1], W2SCALE_INV, b2v[nt].y));
                r1.x = swish_f(fmaf(d[m][nt][2], W2SCALE_INV, b2v[nt].x));
                r1.y = swish_f(fmaf(d[m][nt][3], W2SCALE_INV, b2v[nt].y));
                *(float2*)(orow0 + o) = r0;
                *(float2*)(orow1 + o) = r1;
            }
        }
    }
}

extern "C" void kernel_launch(void* const* d_in, const int* in_sizes, int n_in,
                              void* d_out, int out_size) {
    const float* Edges  = (const float*)d_in[0];
    const float* Coords = (const float*)d_in[1];
    const float* Emb    = (const float*)d_in[2];
    const float* W1     = (const float*)d_in[3];
    const float* b1     = (const float*)d_in[4];
    const float* W2     = (const float*)d_in[5];
    const float* b2     = (const float*)d_in[6];
    float* out = (float*)d_out;

    precompute_AB<<<NN / 8, 512>>>(Emb, W1);
    phi_mma_kernel<<<GRID, THREADS>>>(Edges, Coords, b1, W2, b2, out);
}